// round 15
// baseline (speedup 1.0000x reference)
#include <cuda_runtime.h>
#include <cuda_bf16.h>
#include <math.h>

#define CELLN 14
#define NCLS  80
#define BPC   3
#define FEAT  95            // 80 + 3 + 12
#define CELLS2 196          // 14*14
#define PRED_PER_B 18620    // 196*95
#define CSF   32.0f
#define IMGF  448.0f
#define EPSF  1e-9f
#define INV_PI2_4 0.40528473456935109f   // 4/pi^2
#define MAXB  4096
#define CPAD  32            // g_conf padding: 128B per batch

__device__ float  g_ssum[MAXB * CELLS2];   // per (batch,cell): class sumsq
__device__ float  g_conf[MAXB * CPAD];     // per-batch conf sumsq (128B stride)
__device__ float2 g_part[MAXB * 64];       // per-(b,o): {pk_sum, ciou contrib}
__device__ float  g_accum = 0.0f;          // final accumulator (reset by last block)
__device__ int    g_count = 0;             // finish-kernel arrivals (reset by last block)

// ---------------------------------------------------------------------------
// Kernel 1 (hetero): gather blocks FIRST (overlap with stream), stats after.
//  gather role: 8 threads/(b,o) — pk mask-sum + CIoU/object/coord contrib.
//               Depends ONLY on predicts/labels (not on stats) -> no sync.
//  stats role : warp per 2 cells, trip count 1 (proven streaming shape).
// ---------------------------------------------------------------------------
__global__ __launch_bounds__(256)
void fused_kernel(const float* __restrict__ P,
                  const float* __restrict__ labels,
                  int B, int M, int ncells, int nGather)
{
    const int blk  = blockIdx.x;
    const int tid  = threadIdx.x;
    const int lane = tid & 31;

    if (blk >= nGather) {
        // ================== STATS ROLE ==================
        const int wg = (blk - nGather) * 8 + (tid >> 5);
        const int c0 = wg * 2;
        if (c0 >= ncells) return;

        const float* p0 = P + (size_t)c0 * FEAT;
        const float* p1 = p0 + FEAT;
        const float a0 = p0[lane], b0 = p0[lane + 32], q0 = (lane < 31) ? p0[lane + 64] : 0.0f;
        const float a1 = p1[lane], b1 = p1[lane + 32], q1 = (lane < 31) ? p1[lane + 64] : 0.0f;

        float cls0 = a0 * a0 + b0 * b0;
        float cls1 = a1 * a1 + b1 * b1;
        float conf = 0.0f;
        const float q02 = q0 * q0, q12 = q1 * q1;
        if (lane < 16)      { cls0 += q02;  cls1 += q12; }
        else if (lane < 19) { conf  = q02 + q12; }

        #pragma unroll
        for (int off = 16; off; off >>= 1) {
            cls0 += __shfl_xor_sync(0xFFFFFFFFu, cls0, off);
            cls1 += __shfl_xor_sync(0xFFFFFFFFu, cls1, off);
            conf += __shfl_xor_sync(0xFFFFFFFFu, conf, off);
        }
        if (lane == 0) {
            g_ssum[c0]     = cls0;
            g_ssum[c0 + 1] = cls1;
            atomicAdd(&g_conf[(c0 / CELLS2) * CPAD], conf);
        }
        return;
    }

    // ================== GATHER ROLE ==================
    const int gt   = blk * 256 + tid;
    const int gr   = gt >> 3;
    const int sub  = gt & 7;
    const int nwork = B * M;
    const bool inrange = (gr < nwork);
    const int g    = inrange ? gr : (nwork - 1);

    const int b = g / M;
    const float* lb = labels + (size_t)g * 5;
    const float x = lb[0], y = lb[1], w = lb[2], h = lb[3];
    const int   k = (int)lb[4];

    // center-cell loads first (overlap with mask loads)
    const int cx = (int)floorf(x * (1.0f / CSF));
    const int cy = (int)floorf(y * (1.0f / CSF));
    const float* pb = P + (size_t)b * PRED_PER_B;
    const float* pc = pb + (cy * CELLN + cx) * FEAT;
    const int jb = (sub < BPC) ? sub : 0;

    const float pC  = __ldg(pc + NCLS + jb);
    const float* bxp = pc + NCLS + BPC + 4 * jb;
    const float bx0 = __ldg(bxp + 0), bx1 = __ldg(bxp + 1);
    const float bx2 = __ldg(bxp + 2), bx3 = __ldg(bxp + 3);

    int ix0 = (int)floorf((x - 0.5f * w) * (1.0f / CSF));
    int ix1 = (int)fminf(ceilf((x + 0.5f * w) * (1.0f / CSF)), (float)CELLN);
    int iy0 = (int)floorf((y - 0.5f * h) * (1.0f / CSF));
    int iy1 = (int)fminf(ceilf((y + 0.5f * h) * (1.0f / CSF)), (float)CELLN);
    ix0 = max(ix0, 0); iy0 = max(iy0, 0);
    const int nx  = max(0, ix1 - ix0);
    const int cnt = nx * max(0, iy1 - iy0);

    // pk mask-sum: stride 8 across group, 4 unrolled slots (cnt <= 25)
    float pk = 0.0f;
    #pragma unroll
    for (int jj = 0; jj < 4; jj++) {
        const int t = sub + jj * 8;
        if (t < cnt) {
            const int iy = iy0 + t / nx;
            const int ix = ix0 + t % nx;
            pk += __ldg(pb + (iy * CELLN + ix) * FEAT + k);
        }
    }
    pk += __shfl_xor_sync(0xFFFFFFFFu, pk, 1);
    pk += __shfl_xor_sync(0xFFFFFFFFu, pk, 2);
    pk += __shfl_xor_sync(0xFFFFFFFFu, pk, 4);

    const float px = bx0 * CSF + (float)cx * CSF;
    const float py = bx1 * CSF + (float)cy * CSF;
    const float pw = bx2 * IMGF;
    const float ph = bx3 * IMGF;

    // CIoU exactly per reference (incl. centers-vs-widths enclose quirk)
    float ciou;
    {
        const float x11 = px - 0.5f * pw, x12 = px + 0.5f * pw;
        const float y11 = py - 0.5f * ph, y12 = py + 0.5f * ph;
        const float x21 = x - 0.5f * w,   x22 = x + 0.5f * w;
        const float y21 = y - 0.5f * h,   y22 = y + 0.5f * h;
        const float iw = fmaxf(fminf(x12, x22) - fmaxf(x11, x21), 0.0f);
        const float ih = fmaxf(fminf(y12, y22) - fmaxf(y11, y21), 0.0f);
        const float inter = iw * ih;
        const float uni = pw * ph + w * h - inter;
        const float iou = inter / (uni + EPSF);
        const float cd  = (px - x) * (px - x) + (py - y) * (py - y);
        const float el = fminf(px, x), er = fmaxf(pw, w);
        const float et = fminf(py, y), eb = fmaxf(ph, h);
        const float ed = (er - el) * (er - el) + (eb - et) * (eb - et);
        const float da = atanf(w / (h + EPSF)) - atanf(pw / (ph + EPSF));
        const float v  = INV_PI2_4 * da * da;
        const float alpha = v / (1.0f - iou + v + EPSF);
        ciou = iou - cd / (ed + EPSF) - alpha * v;
    }
    const float my_ciou = (sub < BPC) ? ciou : -1e30f;

    float m = my_ciou;
    m = fmaxf(m, __shfl_xor_sync(0xFFFFFFFFu, m, 1));
    m = fmaxf(m, __shfl_xor_sync(0xFFFFFFFFu, m, 2));
    m = fmaxf(m, __shfl_xor_sync(0xFFFFFFFFu, m, 4));

    float contrib = 0.0f;
    if (sub < BPC && my_ciou >= m) {
        const float d = pC - ciou;
        contrib += 0.5f * d * d;               // object loss
        contrib -= 0.25f * pC * pC;            // removed from noobject term
        const float dx = (px - x) * (1.0f / CSF);
        const float dy = (py - y) * (1.0f / CSF);
        const float swp = sqrtf(fminf(fmaxf(pw, 0.0f), IMGF));
        const float shp = sqrtf(fminf(fmaxf(ph, 0.0f), IMGF));
        const float dw = swp - sqrtf(fabsf(w));
        const float dh = shp - sqrtf(fabsf(h));
        contrib += 5.0f * (0.5f * dx * dx + 0.5f * dy * dy
                           + (0.5f * dw * dw) * (1.0f / IMGF)
                           + (0.5f * dh * dh) * (1.0f / IMGF));
    }
    contrib += __shfl_xor_sync(0xFFFFFFFFu, contrib, 1);
    contrib += __shfl_xor_sync(0xFFFFFFFFu, contrib, 2);
    contrib += __shfl_xor_sync(0xFFFFFFFFu, contrib, 4);

    if (inrange && sub == 0)
        g_part[g] = make_float2(pk, contrib);
}

// ---------------------------------------------------------------------------
// Kernel 2 (finish): 8 threads/(b,o), everything L2-hot (g_ssum just written,
// g_part, labels). cls = sum_mask(ssum+1) - 2*pk; + conf term; reduce.
// ---------------------------------------------------------------------------
__global__ __launch_bounds__(256)
void finish_kernel(const float* __restrict__ labels,
                   const int*   __restrict__ objects_num,
                   float* __restrict__ out, int B, int M, int nblocks)
{
    __shared__ float swarp[8];
    __shared__ int   s_last;

    const int tid  = threadIdx.x;
    const int lane = tid & 31;
    const int wid  = tid >> 5;
    const int gt   = blockIdx.x * 256 + tid;
    const int gr   = gt >> 3;
    const int sub  = gt & 7;
    const int nwork = B * M;
    const bool inrange = (gr < nwork);
    const int g    = inrange ? gr : (nwork - 1);

    const int b = g / M;
    const int o = g - b * M;
    int nobj = objects_num[b];
    if (nobj > M) nobj = M;
    const bool valid = inrange && (o < nobj);

    float loss = 0.0f;
    if (inrange && o == 0 && sub == 0) {
        const float cv = g_conf[b * CPAD];
        g_conf[b * CPAD] = 0.0f;              // reset for next graph replay
        loss += 0.25f * cv * (float)nobj;     // noobject full-grid term x nobj
    }

    const float* lb = labels + (size_t)g * 5;
    const float x = lb[0], y = lb[1], w = lb[2], h = lb[3];

    int ix0 = (int)floorf((x - 0.5f * w) * (1.0f / CSF));
    int ix1 = (int)fminf(ceilf((x + 0.5f * w) * (1.0f / CSF)), (float)CELLN);
    int iy0 = (int)floorf((y - 0.5f * h) * (1.0f / CSF));
    int iy1 = (int)fminf(ceilf((y + 0.5f * h) * (1.0f / CSF)), (float)CELLN);
    ix0 = max(ix0, 0); iy0 = max(iy0, 0);
    const int nx  = max(0, ix1 - ix0);
    const int cnt = nx * max(0, iy1 - iy0);

    const float* ss = g_ssum + b * CELLS2;

    float cs = 0.0f;                           // sum of (ssum + 1) over mask
    #pragma unroll
    for (int jj = 0; jj < 4; jj++) {
        const int t = sub + jj * 8;
        if (t < cnt) {
            const int iy = iy0 + t / nx;
            const int ix = ix0 + t % nx;
            cs += __ldg(ss + iy * CELLN + ix) + 1.0f;
        }
    }
    cs += __shfl_xor_sync(0xFFFFFFFFu, cs, 1);
    cs += __shfl_xor_sync(0xFFFFFFFFu, cs, 2);
    cs += __shfl_xor_sync(0xFFFFFFFFu, cs, 4);

    if (valid && sub == 0) {
        const float2 part = g_part[g];
        loss += 0.5f * (cs - 2.0f * part.x) + part.y;
    }

    #pragma unroll
    for (int off = 16; off; off >>= 1)
        loss += __shfl_xor_sync(0xFFFFFFFFu, loss, off);
    if (lane == 0) swarp[wid] = loss;
    __syncthreads();
    if (tid == 0) {
        float s = 0.0f;
        #pragma unroll
        for (int i = 0; i < 8; i++) s += swarp[i];
        atomicAdd(&g_accum, s);
        __threadfence();
        s_last = (atomicAdd(&g_count, 1) == nblocks - 1);
    }
    __syncthreads();

    if (s_last && tid == 0) {
        __threadfence();
        out[0] = g_accum / (float)B;
        g_accum = 0.0f;                       // reset for next graph replay
        g_count = 0;
    }
}

extern "C" void kernel_launch(void* const* d_in, const int* in_sizes, int n_in,
                              void* d_out, int out_size)
{
    const float* predicts = (const float*)d_in[0];
    const float* labels   = (const float*)d_in[1];
    const int*   objnum   = (const int*)d_in[2];
    float* out = (float*)d_out;

    const int B = in_sizes[2];
    const int M = in_sizes[1] / (B * 5);
    const int ncells = B * CELLS2;

    const int nGather = (B * M * 8 + 255) / 256;           // 960
    const int nStats  = ((ncells + 1) / 2 + 7) / 8;        // 12544
    const int gridF   = (B * M * 8 + 255) / 256;

    fused_kernel<<<nGather + nStats, 256>>>(predicts, labels, B, M, ncells, nGather);
    finish_kernel<<<gridF, 256>>>(labels, objnum, out, B, M, gridF);
}